// round 8
// baseline (speedup 1.0000x reference)
#include <cuda_runtime.h>
#include <cstdint>

#define NQ   22
#define DIM  (1u << NQ)     // 4194304 elements per component

// ---- tiny diagonal split tables (device globals, no allocation) ----
// diag[b] = dLo[b&2047] + dHi[b>>11] + sum_{h set in (b>>11)} R[h][b&2047]
__device__ float g_dLo[2048];
__device__ float g_dHi[2048];
__device__ float g_R[11][2048];

__device__ __forceinline__ void add4(float4& a, const float4 b) {
    a.x += b.x; a.y += b.y; a.z += b.z; a.w += b.w;
}

__device__ __forceinline__ uint32_t smem_u32(const void* p) {
    uint32_t a;
    asm("{ .reg .u64 t; cvta.to.shared.u64 t, %1; cvt.u32.u64 %0, t; }"
        : "=r"(a) : "l"(p));
    return a;
}
__device__ __forceinline__ void cpasync16(uint32_t s, const void* g) {
    asm volatile("cp.async.cg.shared.global [%0], [%1], 16;" :: "r"(s), "l"(g));
}
#define CP_COMMIT() asm volatile("cp.async.commit_group;")
#define CP_WAIT0()  asm volatile("cp.async.wait_group 0;")

// ---------------------------------------------------------------------------
// Diag tables, computed by K1 CTAs 0..3 (512 entries each), read only by K2.
// ---------------------------------------------------------------------------
__device__ void compute_tables(const float* __restrict__ U,
                               const float* __restrict__ detune,
                               float* sU /* >= 485 floats */)
{
    for (int i = threadIdx.x; i < NQ * NQ; i += 512) sU[i] = U[i];
    if (threadIdx.x == 0) sU[NQ * NQ] = detune[0];
    __syncthreads();
    const float det = sU[NQ * NQ];
    const int t = blockIdx.x * 512 + threadIdx.x;   // 0..2047

    float dlo = 0.f;
#pragma unroll
    for (int p = 0; p < 11; p++) {
        if ((t >> p) & 1) {
            dlo -= det;
#pragma unroll
            for (int q = 0; q < p; q++)
                if ((t >> q) & 1) dlo += sU[(21 - p) * NQ + (21 - q)];
        }
    }
    g_dLo[t] = dlo;

    float dhi = 0.f;
#pragma unroll
    for (int h = 0; h < 11; h++) {
        if ((t >> h) & 1) {
            dhi -= det;
#pragma unroll
            for (int h2 = 0; h2 < h; h2++)
                if ((t >> h2) & 1) dhi += sU[(10 - h) * NQ + (10 - h2)];
        }
    }
    g_dHi[t] = dhi;

#pragma unroll
    for (int h = 0; h < 11; h++) {
        float r = 0.f;
#pragma unroll
        for (int q = 0; q < 11; q++)
            if ((t >> q) & 1) r += sU[(10 - h) * NQ + (21 - q)];
        g_R[h][t] = r;
    }
}

// ---------------------------------------------------------------------------
// K1: low bits 0..12 (13 X-neighbors), writes out = c*acc (fresh). No diag.
//   64KB tile (8192 consecutive elems), grid 512, 512 thr, 2 CTAs/SM.
//   bits 0..1: in-float4; bits 2..10: 9 smem dirs; bits 11..12: reg dirs.
//   Neighbor sums tree-reduced to cut dependent-chain depth.
// ---------------------------------------------------------------------------
__global__ void __launch_bounds__(512, 2)
k1_low_kernel(const float* __restrict__ sr, const float* __restrict__ si,
              const float* __restrict__ rabi, float* __restrict__ out,
              const float* __restrict__ U, const float* __restrict__ detune)
{
    extern __shared__ float4 smem[];   // [2048 r][2048 i] = 64KB
    __shared__ float sU[NQ * NQ + 1];
    const uint32_t sb = smem_u32(smem);
    const int tid = threadIdx.x;
    const unsigned gbase = (unsigned)blockIdx.x << 11;
    const float4* grp = (const float4*)sr;
    const float4* gip = (const float4*)si;

#pragma unroll
    for (int j = 0; j < 4; j++) {
        const int idx = tid + j * 512;
        cpasync16(sb + idx * 16, grp + gbase + idx);
        cpasync16(sb + 32768 + idx * 16, gip + gbase + idx);
    }
    CP_COMMIT();
    const float c = 0.5f * __ldg(rabi);

    if (blockIdx.x < 4) compute_tables(U, detune, sU);

    CP_WAIT0();
    __syncthreads();

#pragma unroll
    for (int comp = 0; comp < 2; comp++) {
        const float4* sv = smem + comp * 2048;
        float4* o4 = (float4*)(out + comp * DIM);

        float4 v[4];
#pragma unroll
        for (int k = 0; k < 4; k++) v[k] = sv[tid + k * 512];

#pragma unroll
        for (int k = 0; k < 4; k++) {
            const int G = tid + k * 512;
            const float4 s = v[k];

            // 9 smem dirs (bits 2..10) loaded up front
            float4 t0 = sv[G ^ 1],   t1 = sv[G ^ 2],   t2 = sv[G ^ 4];
            float4 t3 = sv[G ^ 8],   t4 = sv[G ^ 16],  t5 = sv[G ^ 32];
            float4 t6 = sv[G ^ 64],  t7 = sv[G ^ 128], t8 = sv[G ^ 256];

            // bits 0..1 (in-float4) as tree leaf
            float4 a = make_float4(s.y + s.z, s.x + s.w, s.w + s.x, s.z + s.y);

            // tree reduction
            add4(t0, t1); add4(t2, t3); add4(t4, t5); add4(t6, t7);
            add4(t8, v[k ^ 1]); add4(a, v[k ^ 2]);
            add4(t0, t2); add4(t4, t6); add4(t8, a);
            add4(t0, t4); add4(t0, t8);

            o4[gbase + G] = make_float4(c * t0.x, c * t0.y, c * t0.z, c * t0.w);
        }
    }
}

// ---------------------------------------------------------------------------
// K2: high bits 13..21 (9 X-neighbors) + diagonal, RMW into out.
//   mid = elem bits 4..12 (grid 512); tile = 512 combos (bits 13..21) x 16
//   consecutive elems. idx = tid + k*512: rf4 = tid&3, combo = (tid>>2)|k<<7.
//   bits 13..19: 7 smem dirs; bits 20..21: reg dirs k^1,k^2.
//   RMW out values prefetched with __ldcs before the LDS phase; final
//   stores are __stcs (streaming) to spare L2 for psi.
// ---------------------------------------------------------------------------
__global__ void __launch_bounds__(512, 2)
k2_high_kernel(const float* __restrict__ sr, const float* __restrict__ si,
               const float* __restrict__ rabi, float* __restrict__ out)
{
    extern __shared__ float4 smem[];   // [2048 r][2048 i] = 64KB
    const uint32_t sb = smem_u32(smem);
    const int tid = threadIdx.x;
    const unsigned mid = blockIdx.x;               // elem bits 4..12
    const int rf4 = tid & 3;
    const int cb7 = tid >> 2;                      // combo bits 0..6
    const float4* grp = (const float4*)sr;
    const float4* gip = (const float4*)si;

#pragma unroll
    for (int j = 0; j < 4; j++) {
        const int idx = tid + j * 512;
        const unsigned gG = ((unsigned)(idx >> 2) << 11) + (mid << 2) + (idx & 3);
        cpasync16(sb + idx * 16, grp + gG);
        cpasync16(sb + 32768 + idx * 16, gip + gG);
    }
    CP_COMMIT();
    const float c = 0.5f * __ldg(rabi);

    // ---- diag staging (L1 loads; overlaps the cp.async fill) ----
    const int lo4 = ((int)(mid & 127u) << 4) | (rf4 << 2);
    const int midhi = (int)(mid >> 7);             // hi bits 0..1
    float4 base4 = __ldg((const float4*)&g_dLo[lo4]);
    if (midhi & 1) add4(base4, __ldg((const float4*)&g_R[0][lo4]));
    if (midhi & 2) add4(base4, __ldg((const float4*)&g_R[1][lo4]));
#pragma unroll
    for (int t = 0; t < 7; t++)
        if ((cb7 >> t) & 1) add4(base4, __ldg((const float4*)&g_R[t + 2][lo4]));
    const float4 r9  = __ldg((const float4*)&g_R[9][lo4]);
    const float4 r10 = __ldg((const float4*)&g_R[10][lo4]);
    float dh0 = __ldg(&g_dHi[(((unsigned)cb7          << 2) | midhi)]);
    float dh1 = __ldg(&g_dHi[(((unsigned)(cb7 | 128u) << 2) | midhi)]);
    float dh2 = __ldg(&g_dHi[(((unsigned)(cb7 | 256u) << 2) | midhi)]);
    float dh3 = __ldg(&g_dHi[(((unsigned)(cb7 | 384u) << 2) | midhi)]);

    CP_WAIT0();
    __syncthreads();

#pragma unroll
    for (int comp = 0; comp < 2; comp++) {
        const float4* sv = smem + comp * 2048;
        float4* o4 = (float4*)(out + comp * DIM);

        // prefetch RMW targets early so L2/DRAM latency overlaps LDS work
        float4 o[4];
#pragma unroll
        for (int k = 0; k < 4; k++) {
            const int idx = tid + k * 512;
            const unsigned gG = ((unsigned)(idx >> 2) << 11) + (mid << 2) + (idx & 3);
            o[k] = __ldcs(&o4[gG]);
        }

        float4 v[4];
#pragma unroll
        for (int k = 0; k < 4; k++) v[k] = sv[tid + k * 512];

#pragma unroll
        for (int k = 0; k < 4; k++) {
            const int idx = tid + k * 512;

            // 7 smem dirs (bits 13..19)
            float4 t0 = sv[idx ^ 4],   t1 = sv[idx ^ 8],   t2 = sv[idx ^ 16];
            float4 t3 = sv[idx ^ 32],  t4 = sv[idx ^ 64],  t5 = sv[idx ^ 128];
            float4 t6 = sv[idx ^ 256];

            // tree reduction with reg dirs (bits 20..21)
            add4(t0, t1); add4(t2, t3); add4(t4, t5);
            add4(t6, v[k ^ 1]);
            float4 a = v[k ^ 2];
            add4(t0, t2); add4(t4, t6);
            add4(a, t0); add4(a, t4);

            // diagonal weight
            float4 W = base4;
            if (k & 1) add4(W, r9);
            if (k & 2) add4(W, r10);
            const float dh = (k == 0) ? dh0 : (k == 1) ? dh1 : (k == 2) ? dh2 : dh3;
            W.x += dh; W.y += dh; W.z += dh; W.w += dh;

            float4 oo = o[k];
            oo.x = fmaf(c, a.x, fmaf(W.x, v[k].x, oo.x));
            oo.y = fmaf(c, a.y, fmaf(W.y, v[k].y, oo.y));
            oo.z = fmaf(c, a.z, fmaf(W.z, v[k].z, oo.z));
            oo.w = fmaf(c, a.w, fmaf(W.w, v[k].w, oo.w));
            const unsigned gG = ((unsigned)(idx >> 2) << 11) + (mid << 2) + (idx & 3);
            __stcs(&o4[gG], oo);
        }
    }
}

// ---------------------------------------------------------------------------
// Launch: K1 (low dirs, writes out; CTAs 0..3 build tables)
//      -> K2 (high dirs + diag, RMW out).
// ---------------------------------------------------------------------------
extern "C" void kernel_launch(void* const* d_in, const int* in_sizes, int n_in,
                              void* d_out, int out_size)
{
    const float* sr     = (const float*)d_in[0];
    const float* si     = (const float*)d_in[1];
    const float* rabi   = (const float*)d_in[2];
    const float* detune = (const float*)d_in[3];
    const float* U      = (const float*)d_in[4];
    float* out = (float*)d_out;

    cudaFuncSetAttribute(k1_low_kernel,
                         cudaFuncAttributeMaxDynamicSharedMemorySize, 65536);
    cudaFuncSetAttribute(k2_high_kernel,
                         cudaFuncAttributeMaxDynamicSharedMemorySize, 65536);

    k1_low_kernel<<<512, 512, 65536>>>(sr, si, rabi, out, U, detune);
    k2_high_kernel<<<512, 512, 65536>>>(sr, si, rabi, out);
}